// round 14
// baseline (speedup 1.0000x reference)
#include <cuda_runtime.h>
#include <cuda_fp16.h>
#include <cstdint>

#define NROW 8192
#define DDIM 1024
#define CH 64                     // K per pipeline chunk (64 fp16 = 128 B)
#define KCH (DDIM / CH)           // 16 chunks
#define STAGES 2
#define TM 128                    // CTA tile M
#define TN 128                    // CTA tile N
#define NTM (NROW / TM)           // 64
#define NTN (NROW / TN)           // 64
#define STG_A (TM * 128)          // 16 KB
#define STG_B (TN * 128)          // 16 KB
#define STG_BYTES (STG_A + STG_B) // 32 KB
#define CHUNK_STRIDE ((size_t)NROW * 128)  // 1 MB per k-chunk blob

// ---------------- device scratch ----------------
__device__ __half g_imgn[(size_t)NROW * DDIM];   // chunk-major swizzled, 16 MB
__device__ __half g_txtn[(size_t)NROW * DDIM];   // chunk-major swizzled, 16 MB
__device__ float g_pos[NROW];
__device__ float g_partial[(size_t)NTN * NROW];  // [ntile][row], 2 MB

// ---------------- PTX helpers ----------------
__device__ __forceinline__ uint32_t smem_u32(const void* p) {
    uint32_t a;
    asm("{ .reg .u64 t; cvta.to.shared.u64 t, %1; cvt.u32.u64 %0, t; }" : "=r"(a) : "l"(p));
    return a;
}
__device__ __forceinline__ void mbar_init(uint32_t a, uint32_t c) {
    asm volatile("mbarrier.init.shared.b64 [%0], %1;" :: "r"(a), "r"(c) : "memory");
}
__device__ __forceinline__ void mbar_inval(uint32_t a) {
    asm volatile("mbarrier.inval.shared.b64 [%0];" :: "r"(a) : "memory");
}
__device__ __forceinline__ void mbar_expect_tx(uint32_t a, uint32_t tx) {
    asm volatile("mbarrier.arrive.expect_tx.shared.b64 _, [%0], %1;" :: "r"(a), "r"(tx) : "memory");
}
__device__ __forceinline__ void mbar_arrive(uint32_t a) {
    asm volatile("mbarrier.arrive.shared.b64 _, [%0];" :: "r"(a) : "memory");
}
__device__ __forceinline__ void mbar_wait(uint32_t a, uint32_t parity) {
    asm volatile(
        "{\n\t.reg .pred P;\n\t"
        "WL_%=:\n\t"
        "mbarrier.try_wait.parity.shared.b64 P, [%0], %1;\n\t"
        "@!P bra WL_%=;\n\t}"
        :: "r"(a), "r"(parity) : "memory");
}
__device__ __forceinline__ void bulk_g2s(uint32_t dst, const void* src, uint32_t bytes, uint32_t mbar) {
    asm volatile(
        "cp.async.bulk.shared::cluster.global.mbarrier::complete_tx::bytes [%0], [%1], %2, [%3];"
        :: "r"(dst), "l"(src), "r"(bytes), "r"(mbar) : "memory");
}
__device__ __forceinline__ void ldsm_x4(uint32_t& r0, uint32_t& r1, uint32_t& r2, uint32_t& r3,
                                        uint32_t addr) {
    asm volatile("ldmatrix.sync.aligned.m8n8.x4.shared.b16 {%0,%1,%2,%3}, [%4];"
                 : "=r"(r0), "=r"(r1), "=r"(r2), "=r"(r3) : "r"(addr));
}
// fp16-accumulate HMMA: D(f16x2 pair) = A*B + C
__device__ __forceinline__ void mma16816_f16(uint32_t& c0, uint32_t& c1,
                                             uint32_t a0, uint32_t a1, uint32_t a2, uint32_t a3,
                                             uint32_t b0, uint32_t b1) {
    asm volatile(
        "mma.sync.aligned.m16n8k16.row.col.f16.f16.f16.f16 "
        "{%0,%1}, {%2,%3,%4,%5}, {%6,%7}, {%0,%1};"
        : "+r"(c0), "+r"(c1)
        : "r"(a0), "r"(a1), "r"(a2), "r"(a3), "r"(b0), "r"(b1));
}
// packed half2 exp2 (underscored: h2exp2 collides with cuda_fp16.hpp builtin)
__device__ __forceinline__ __half2 h2exp2_(__half2 x) {
    uint32_t xb = *reinterpret_cast<uint32_t*>(&x);
    uint32_t rb;
    asm("ex2.approx.f16x2 %0, %1;" : "=r"(rb) : "r"(xb));
    return *reinterpret_cast<__half2*>(&rb);
}

// ---------------------------------------------------------------------------
// Kernel 1: L2-normalize -> fp16 chunk-major swizzled + fp32 positives.
// (unchanged from R12/R13)
// ---------------------------------------------------------------------------
__global__ __launch_bounds__(256) void norm_kernel(const float* __restrict__ img,
                                                   const float* __restrict__ txt) {
    const int warp = threadIdx.x >> 5;
    const int lane = threadIdx.x & 31;
    const int row = blockIdx.x * 8 + warp;

    const float4* gA = reinterpret_cast<const float4*>(img + (size_t)row * DDIM);
    const float4* gB = reinterpret_cast<const float4*>(txt + (size_t)row * DDIM);

    uint4 pa[4], pb[4];
    float sii = 0.f, stt = 0.f, sit = 0.f;

    #pragma unroll
    for (int j = 0; j < 4; j++) {
        const int f = 2 * (lane + 32 * j);
        const float4 a0 = gA[f], a1 = gA[f + 1];
        const float4 b0 = gB[f], b1 = gB[f + 1];

        sii += a0.x * a0.x + a0.y * a0.y + a0.z * a0.z + a0.w * a0.w
             + a1.x * a1.x + a1.y * a1.y + a1.z * a1.z + a1.w * a1.w;
        stt += b0.x * b0.x + b0.y * b0.y + b0.z * b0.z + b0.w * b0.w
             + b1.x * b1.x + b1.y * b1.y + b1.z * b1.z + b1.w * b1.w;
        sit += a0.x * b0.x + a0.y * b0.y + a0.z * b0.z + a0.w * b0.w
             + a1.x * b1.x + a1.y * b1.y + a1.z * b1.z + a1.w * b1.w;

        __half2 h;
        h = __floats2half2_rn(a0.x, a0.y); pa[j].x = *reinterpret_cast<uint32_t*>(&h);
        h = __floats2half2_rn(a0.z, a0.w); pa[j].y = *reinterpret_cast<uint32_t*>(&h);
        h = __floats2half2_rn(a1.x, a1.y); pa[j].z = *reinterpret_cast<uint32_t*>(&h);
        h = __floats2half2_rn(a1.z, a1.w); pa[j].w = *reinterpret_cast<uint32_t*>(&h);
        h = __floats2half2_rn(b0.x, b0.y); pb[j].x = *reinterpret_cast<uint32_t*>(&h);
        h = __floats2half2_rn(b0.z, b0.w); pb[j].y = *reinterpret_cast<uint32_t*>(&h);
        h = __floats2half2_rn(b1.x, b1.y); pb[j].z = *reinterpret_cast<uint32_t*>(&h);
        h = __floats2half2_rn(b1.z, b1.w); pb[j].w = *reinterpret_cast<uint32_t*>(&h);
    }

    #pragma unroll
    for (int o = 16; o; o >>= 1) {
        sii += __shfl_xor_sync(0xffffffffu, sii, o);
        stt += __shfl_xor_sync(0xffffffffu, stt, o);
        sit += __shfl_xor_sync(0xffffffffu, sit, o);
    }

    const float inv_i = 1.0f / fmaxf(sqrtf(sii), 1e-12f);
    const float inv_t = 1.0f / fmaxf(sqrtf(stt), 1e-12f);
    const __half2 hi = __float2half2_rn(inv_i);
    const __half2 ht = __float2half2_rn(inv_t);

    #pragma unroll
    for (int j = 0; j < 4; j++) {
        uint4 pi, pt;
        #pragma unroll
        for (int e = 0; e < 4; e++) {
            uint32_t ua = (&pa[j].x)[e];
            uint32_t ub = (&pb[j].x)[e];
            __half2 va = __hmul2(*reinterpret_cast<__half2*>(&ua), hi);
            __half2 vb = __hmul2(*reinterpret_cast<__half2*>(&ub), ht);
            (&pi.x)[e] = *reinterpret_cast<uint32_t*>(&va);
            (&pt.x)[e] = *reinterpret_cast<uint32_t*>(&vb);
        }
        const int p = lane + 32 * j;          // 16B-granule index within row (0..127)
        const int c = p >> 3;                 // k-chunk (8 granules = 64 cols)
        uint32_t off = (uint32_t)row * 128u + (uint32_t)((p & 7) << 4);
        off ^= (off >> 3) & 0x70u;
        const size_t addr = (size_t)c * CHUNK_STRIDE + off;

        *reinterpret_cast<uint4*>(reinterpret_cast<char*>(g_imgn) + addr) = pi;
        *reinterpret_cast<uint4*>(reinterpret_cast<char*>(g_txtn) + addr) = pt;
    }

    if (lane == 0) g_pos[row] = sit * inv_i * inv_t;  // exact fp32 diagonal
}

// ---------------------------------------------------------------------------
// Kernel 2: 3-CTA/SM bulk-async fp16-acc HMMA GEMM + packed-half2 exp rowsum.
// CTA tile 128x128, warp tile 64x32, 2-stage ring (inter-CTA overlap
// replaces pipeline depth). smem 64KB/CTA -> 192KB/SM.
// ---------------------------------------------------------------------------
__global__ __launch_bounds__(256, 3) void gemm_lse_kernel() {
    extern __shared__ __align__(128) char smem[];       // STAGES*32KB (+pad)
    __shared__ __align__(8) unsigned long long full_bar[STAGES], empty_bar[STAGES];
    __shared__ float rowAcc[TM];

    const int tid = threadIdx.x;
    const int warp = tid >> 5;
    const int lane = tid & 31;
    const int wm = warp >> 2;        // 0..1
    const int wn = warp & 3;         // 0..3
    const int mtile = blockIdx.x;    // 64
    const int ntile = blockIdx.y;    // 64

    uint32_t sbase = smem_u32(smem);
    sbase = (sbase + 127u) & ~127u;
    const uint32_t fullb = smem_u32(&full_bar[0]);
    const uint32_t emptyb = smem_u32(&empty_bar[0]);

    if (tid == 0) {
        #pragma unroll
        for (int s = 0; s < STAGES; s++) {
            mbar_init(fullb + 8u * s, 1);
            mbar_init(emptyb + 8u * s, 8);   // one arrive per warp
        }
    }
    if (tid < TM) rowAcc[tid] = 0.0f;
    __syncthreads();

    const char* baseA = reinterpret_cast<const char*>(g_imgn) + (size_t)mtile * STG_A;
    const char* baseB = reinterpret_cast<const char*>(g_txtn) + (size_t)ntile * STG_B;

    // prologue: chunk 0 into slot 0
    if (tid == 0) {
        mbar_expect_tx(fullb, STG_BYTES);
        bulk_g2s(sbase,         baseA, STG_A, fullb);
        bulk_g2s(sbase + STG_A, baseB, STG_B, fullb);
    }

    uint32_t acc[4][4][2];       // f16x2 accumulator fragments (64x32 warp tile)
    #pragma unroll
    for (int mi = 0; mi < 4; mi++)
        #pragma unroll
        for (int ni = 0; ni < 4; ni++) {
            acc[mi][ni][0] = 0u;
            acc[mi][ni][1] = 0u;
        }

    #pragma unroll 2
    for (int c = 0; c < KCH; c++) {
        const int s = c & 1;
        mbar_wait(fullb + 8u * s, (uint32_t)((c >> 1) & 1));

        const uint32_t sa = sbase + (uint32_t)s * STG_BYTES;
        const uint32_t sb = sa + STG_A;

        #pragma unroll
        for (int ks = 0; ks < 4; ks++) {
            uint32_t a[4][4], b[2][4];
            #pragma unroll
            for (int mi = 0; mi < 4; mi++) {
                const int r = wm * 64 + mi * 16 + (lane & 15);
                const int g = 2 * ks + (lane >> 4);
                ldsm_x4(a[mi][0], a[mi][1], a[mi][2], a[mi][3],
                        sa + (uint32_t)r * 128u + (uint32_t)((g ^ (r & 7)) << 4));
            }
            #pragma unroll
            for (int bi = 0; bi < 2; bi++) {
                const int nr = wn * 32 + bi * 16 + (lane & 7) + ((lane >> 4) << 3);
                const int g = 2 * ks + ((lane >> 3) & 1);
                ldsm_x4(b[bi][0], b[bi][1], b[bi][2], b[bi][3],
                        sb + (uint32_t)nr * 128u + (uint32_t)((g ^ (nr & 7)) << 4));
            }
            #pragma unroll
            for (int mi = 0; mi < 4; mi++)
                #pragma unroll
                for (int ni = 0; ni < 4; ni++)
                    mma16816_f16(acc[mi][ni][0], acc[mi][ni][1],
                                 a[mi][0], a[mi][1], a[mi][2], a[mi][3],
                                 b[ni >> 1][(ni & 1) * 2], b[ni >> 1][(ni & 1) * 2 + 1]);
        }

        if (lane == 0) mbar_arrive(emptyb + 8u * s);

        if (tid == 0) {
            const int nx = c + 1;
            if (nx < KCH) {
                const int sn = nx & 1;
                if (nx >= STAGES)
                    mbar_wait(emptyb + 8u * sn, (uint32_t)(((nx - 2) >> 1) & 1));
                const uint32_t st = sbase + (uint32_t)sn * STG_BYTES;
                mbar_expect_tx(fullb + 8u * sn, STG_BYTES);
                bulk_g2s(st,         baseA + (size_t)nx * CHUNK_STRIDE, STG_A, fullb + 8u * sn);
                bulk_g2s(st + STG_A, baseB + (size_t)nx * CHUNK_STRIDE, STG_B, fullb + 8u * sn);
            }
        }
    }

    // Epilogue: exp(v-1) = ex2(v*log2e - log2e), packed half2; per-row reduce.
    const __half2 l2e  = __float2half2_rn(1.44269504f);
    const __half2 noff = __float2half2_rn(-1.44269504f);
    #pragma unroll
    for (int mi = 0; mi < 4; mi++) {
        __half2 t0 = __float2half2_rn(0.0f);
        __half2 t1 = __float2half2_rn(0.0f);
        #pragma unroll
        for (int ni = 0; ni < 4; ni++) {
            __half2 v0 = *reinterpret_cast<__half2*>(&acc[mi][ni][0]);
            __half2 v1 = *reinterpret_cast<__half2*>(&acc[mi][ni][1]);
            t0 = __hadd2(t0, h2exp2_(__hfma2(v0, l2e, noff)));
            t1 = __hadd2(t1, h2exp2_(__hfma2(v1, l2e, noff)));
        }
        float s0 = __low2float(t0) + __high2float(t0);
        float s1 = __low2float(t1) + __high2float(t1);
        s0 += __shfl_xor_sync(0xffffffffu, s0, 1);
        s0 += __shfl_xor_sync(0xffffffffu, s0, 2);
        s1 += __shfl_xor_sync(0xffffffffu, s1, 1);
        s1 += __shfl_xor_sync(0xffffffffu, s1, 2);
        if ((lane & 3) == 0) {
            const int r = wm * 64 + mi * 16 + (lane >> 2);
            atomicAdd(&rowAcc[r], s0);
            atomicAdd(&rowAcc[r + 8], s1);
        }
    }
    __syncthreads();
    if (tid < TM)
        g_partial[(size_t)ntile * NROW + mtile * TM + tid] = rowAcc[tid];

    if (tid == 0) {
        #pragma unroll
        for (int q = 0; q < STAGES; q++) {
            mbar_inval(fullb + 8u * q);
            mbar_inval(emptyb + 8u * q);
        }
    }
}

// ---------------------------------------------------------------------------
// Kernel 3: fused finalize. Single CTA, 1024 threads, 8 rows/thread.
// ---------------------------------------------------------------------------
__global__ __launch_bounds__(1024) void finalize_kernel(float* __restrict__ out) {
    __shared__ float red[1024];
    float tsum = 0.0f;
    #pragma unroll
    for (int i = 0; i < NROW / 1024; i++) {
        const int row = threadIdx.x + i * 1024;
        float s = 0.0f;
        #pragma unroll
        for (int p = 0; p < NTN; p++) s += g_partial[(size_t)p * NROW + row];
        tsum += logf(s) - g_pos[row];
    }
    red[threadIdx.x] = tsum;
    __syncthreads();
    #pragma unroll
    for (int off = 512; off > 0; off >>= 1) {
        if (threadIdx.x < off) red[threadIdx.x] += red[threadIdx.x + off];
        __syncthreads();
    }
    if (threadIdx.x == 0) out[0] = red[0] / (float)NROW;
}

// ---------------------------------------------------------------------------
extern "C" void kernel_launch(void* const* d_in, const int* in_sizes, int n_in,
                              void* d_out, int out_size) {
    const float* img = (const float*)d_in[0];
    const float* txt = (const float*)d_in[1];
    float* out = (float*)d_out;

    norm_kernel<<<NROW / 8, 256>>>(img, txt);

    cudaFuncSetAttribute(gemm_lse_kernel,
                         cudaFuncAttributeMaxDynamicSharedMemorySize,
                         STAGES * STG_BYTES + 128);
    dim3 grid(NTM, NTN);
    gemm_lse_kernel<<<grid, 256, STAGES * STG_BYTES + 128>>>();

    finalize_kernel<<<1, 1024>>>(out);
}

// round 15
// speedup vs baseline: 1.0668x; 1.0668x over previous
#include <cuda_runtime.h>
#include <cuda_fp16.h>
#include <cstdint>

#define NROW 8192
#define DDIM 1024
#define CH 64                     // K per pipeline chunk (64 fp16 = 128 B)
#define KCH (DDIM / CH)           // 16 chunks
#define STAGES 3
#define TM 128                    // CTA tile M
#define TN 128                    // CTA tile N
#define NTM (NROW / TM)           // 64
#define NTN (NROW / TN)           // 64
#define STG_A (TM * 128)          // 16 KB
#define STG_B (TN * 128)          // 16 KB
#define STG_BYTES (STG_A + STG_B) // 32 KB
#define CHUNK_STRIDE ((size_t)NROW * 128)  // 1 MB per k-chunk blob
#define FIN_BLOCKS 32

// ---------------- device scratch ----------------
__device__ __half g_imgn[(size_t)NROW * DDIM];   // chunk-major swizzled, 16 MB
__device__ __half g_txtn[(size_t)NROW * DDIM];   // chunk-major swizzled, 16 MB
__device__ float g_pos[NROW];
__device__ float g_partial[(size_t)NTN * NROW];  // [ntile][row], 2 MB
__device__ float g_bsum[FIN_BLOCKS];

// ---------------- PTX helpers ----------------
__device__ __forceinline__ uint32_t smem_u32(const void* p) {
    uint32_t a;
    asm("{ .reg .u64 t; cvta.to.shared.u64 t, %1; cvt.u32.u64 %0, t; }" : "=r"(a) : "l"(p));
    return a;
}
__device__ __forceinline__ void mbar_init(uint32_t a, uint32_t c) {
    asm volatile("mbarrier.init.shared.b64 [%0], %1;" :: "r"(a), "r"(c) : "memory");
}
__device__ __forceinline__ void mbar_inval(uint32_t a) {
    asm volatile("mbarrier.inval.shared.b64 [%0];" :: "r"(a) : "memory");
}
__device__ __forceinline__ void mbar_expect_tx(uint32_t a, uint32_t tx) {
    asm volatile("mbarrier.arrive.expect_tx.shared.b64 _, [%0], %1;" :: "r"(a), "r"(tx) : "memory");
}
__device__ __forceinline__ void mbar_arrive(uint32_t a) {
    asm volatile("mbarrier.arrive.shared.b64 _, [%0];" :: "r"(a) : "memory");
}
__device__ __forceinline__ void mbar_wait(uint32_t a, uint32_t parity) {
    asm volatile(
        "{\n\t.reg .pred P;\n\t"
        "WL_%=:\n\t"
        "mbarrier.try_wait.parity.shared.b64 P, [%0], %1;\n\t"
        "@!P bra WL_%=;\n\t}"
        :: "r"(a), "r"(parity) : "memory");
}
__device__ __forceinline__ void bulk_g2s(uint32_t dst, const void* src, uint32_t bytes, uint32_t mbar) {
    asm volatile(
        "cp.async.bulk.shared::cluster.global.mbarrier::complete_tx::bytes [%0], [%1], %2, [%3];"
        :: "r"(dst), "l"(src), "r"(bytes), "r"(mbar) : "memory");
}
__device__ __forceinline__ void ldsm_x4(uint32_t& r0, uint32_t& r1, uint32_t& r2, uint32_t& r3,
                                        uint32_t addr) {
    asm volatile("ldmatrix.sync.aligned.m8n8.x4.shared.b16 {%0,%1,%2,%3}, [%4];"
                 : "=r"(r0), "=r"(r1), "=r"(r2), "=r"(r3) : "r"(addr));
}
// fp16-accumulate HMMA: D(f16x2 pair) = A*B + C
__device__ __forceinline__ void mma16816_f16(uint32_t& c0, uint32_t& c1,
                                             uint32_t a0, uint32_t a1, uint32_t a2, uint32_t a3,
                                             uint32_t b0, uint32_t b1) {
    asm volatile(
        "mma.sync.aligned.m16n8k16.row.col.f16.f16.f16.f16 "
        "{%0,%1}, {%2,%3,%4,%5}, {%6,%7}, {%0,%1};"
        : "+r"(c0), "+r"(c1)
        : "r"(a0), "r"(a1), "r"(a2), "r"(a3), "r"(b0), "r"(b1));
}
// packed half2 exp2 (underscored: h2exp2 collides with cuda_fp16.hpp builtin)
__device__ __forceinline__ __half2 h2exp2_(__half2 x) {
    uint32_t xb = *reinterpret_cast<uint32_t*>(&x);
    uint32_t rb;
    asm("ex2.approx.f16x2 %0, %1;" : "=r"(rb) : "r"(xb));
    return *reinterpret_cast<__half2*>(&rb);
}

// ---------------------------------------------------------------------------
// Kernel 1: L2-normalize -> fp16 chunk-major swizzled + fp32 positives.
// (unchanged from R12/R13)
// ---------------------------------------------------------------------------
__global__ __launch_bounds__(256) void norm_kernel(const float* __restrict__ img,
                                                   const float* __restrict__ txt) {
    const int warp = threadIdx.x >> 5;
    const int lane = threadIdx.x & 31;
    const int row = blockIdx.x * 8 + warp;

    const float4* gA = reinterpret_cast<const float4*>(img + (size_t)row * DDIM);
    const float4* gB = reinterpret_cast<const float4*>(txt + (size_t)row * DDIM);

    uint4 pa[4], pb[4];
    float sii = 0.f, stt = 0.f, sit = 0.f;

    #pragma unroll
    for (int j = 0; j < 4; j++) {
        const int f = 2 * (lane + 32 * j);
        const float4 a0 = gA[f], a1 = gA[f + 1];
        const float4 b0 = gB[f], b1 = gB[f + 1];

        sii += a0.x * a0.x + a0.y * a0.y + a0.z * a0.z + a0.w * a0.w
             + a1.x * a1.x + a1.y * a1.y + a1.z * a1.z + a1.w * a1.w;
        stt += b0.x * b0.x + b0.y * b0.y + b0.z * b0.z + b0.w * b0.w
             + b1.x * b1.x + b1.y * b1.y + b1.z * b1.z + b1.w * b1.w;
        sit += a0.x * b0.x + a0.y * b0.y + a0.z * b0.z + a0.w * b0.w
             + a1.x * b1.x + a1.y * b1.y + a1.z * b1.z + a1.w * b1.w;

        __half2 h;
        h = __floats2half2_rn(a0.x, a0.y); pa[j].x = *reinterpret_cast<uint32_t*>(&h);
        h = __floats2half2_rn(a0.z, a0.w); pa[j].y = *reinterpret_cast<uint32_t*>(&h);
        h = __floats2half2_rn(a1.x, a1.y); pa[j].z = *reinterpret_cast<uint32_t*>(&h);
        h = __floats2half2_rn(a1.z, a1.w); pa[j].w = *reinterpret_cast<uint32_t*>(&h);
        h = __floats2half2_rn(b0.x, b0.y); pb[j].x = *reinterpret_cast<uint32_t*>(&h);
        h = __floats2half2_rn(b0.z, b0.w); pb[j].y = *reinterpret_cast<uint32_t*>(&h);
        h = __floats2half2_rn(b1.x, b1.y); pb[j].z = *reinterpret_cast<uint32_t*>(&h);
        h = __floats2half2_rn(b1.z, b1.w); pb[j].w = *reinterpret_cast<uint32_t*>(&h);
    }

    #pragma unroll
    for (int o = 16; o; o >>= 1) {
        sii += __shfl_xor_sync(0xffffffffu, sii, o);
        stt += __shfl_xor_sync(0xffffffffu, stt, o);
        sit += __shfl_xor_sync(0xffffffffu, sit, o);
    }

    const float inv_i = 1.0f / fmaxf(sqrtf(sii), 1e-12f);
    const float inv_t = 1.0f / fmaxf(sqrtf(stt), 1e-12f);
    const __half2 hi = __float2half2_rn(inv_i);
    const __half2 ht = __float2half2_rn(inv_t);

    #pragma unroll
    for (int j = 0; j < 4; j++) {
        uint4 pi, pt;
        #pragma unroll
        for (int e = 0; e < 4; e++) {
            uint32_t ua = (&pa[j].x)[e];
            uint32_t ub = (&pb[j].x)[e];
            __half2 va = __hmul2(*reinterpret_cast<__half2*>(&ua), hi);
            __half2 vb = __hmul2(*reinterpret_cast<__half2*>(&ub), ht);
            (&pi.x)[e] = *reinterpret_cast<uint32_t*>(&va);
            (&pt.x)[e] = *reinterpret_cast<uint32_t*>(&vb);
        }
        const int p = lane + 32 * j;          // 16B-granule index within row (0..127)
        const int c = p >> 3;                 // k-chunk (8 granules = 64 cols)
        uint32_t off = (uint32_t)row * 128u + (uint32_t)((p & 7) << 4);
        off ^= (off >> 3) & 0x70u;
        const size_t addr = (size_t)c * CHUNK_STRIDE + off;

        *reinterpret_cast<uint4*>(reinterpret_cast<char*>(g_imgn) + addr) = pi;
        *reinterpret_cast<uint4*>(reinterpret_cast<char*>(g_txtn) + addr) = pt;
    }

    if (lane == 0) g_pos[row] = sit * inv_i * inv_t;  // exact fp32 diagonal
}

// ---------------------------------------------------------------------------
// Kernel 2: 2-CTA/SM bulk-async fp16-acc HMMA GEMM + packed-half2 exp rowsum.
// CTA tile 128x128, warp tile 64x32, 3-stage ring. (exact R13 winner)
// ---------------------------------------------------------------------------
__global__ __launch_bounds__(256, 2) void gemm_lse_kernel() {
    extern __shared__ __align__(128) char smem[];       // STAGES*32KB (+pad)
    __shared__ __align__(8) unsigned long long full_bar[STAGES], empty_bar[STAGES];
    __shared__ float rowAcc[TM];

    const int tid = threadIdx.x;
    const int warp = tid >> 5;
    const int lane = tid & 31;
    const int wm = warp >> 2;        // 0..1
    const int wn = warp & 3;         // 0..3
    const int mtile = blockIdx.x;    // 64
    const int ntile = blockIdx.y;    // 64

    uint32_t sbase = smem_u32(smem);
    sbase = (sbase + 127u) & ~127u;
    const uint32_t fullb = smem_u32(&full_bar[0]);
    const uint32_t emptyb = smem_u32(&empty_bar[0]);

    if (tid == 0) {
        #pragma unroll
        for (int s = 0; s < STAGES; s++) {
            mbar_init(fullb + 8u * s, 1);
            mbar_init(emptyb + 8u * s, 8);   // one arrive per warp
        }
    }
    if (tid < TM) rowAcc[tid] = 0.0f;
    __syncthreads();

    const char* baseA = reinterpret_cast<const char*>(g_imgn) + (size_t)mtile * STG_A;
    const char* baseB = reinterpret_cast<const char*>(g_txtn) + (size_t)ntile * STG_B;

    if (tid == 0) {
        #pragma unroll
        for (int c = 0; c < STAGES - 1; c++) {
            const uint32_t st = sbase + (uint32_t)c * STG_BYTES;
            mbar_expect_tx(fullb + 8u * c, STG_BYTES);
            bulk_g2s(st,         baseA + (size_t)c * CHUNK_STRIDE, STG_A, fullb + 8u * c);
            bulk_g2s(st + STG_A, baseB + (size_t)c * CHUNK_STRIDE, STG_B, fullb + 8u * c);
        }
    }

    uint32_t acc[4][4][2];       // f16x2 accumulator fragments (64x32 warp tile)
    #pragma unroll
    for (int mi = 0; mi < 4; mi++)
        #pragma unroll
        for (int ni = 0; ni < 4; ni++) {
            acc[mi][ni][0] = 0u;
            acc[mi][ni][1] = 0u;
        }

    int s = 0, ph = 0;               // consumer slot/parity cursor
    #pragma unroll 3
    for (int c = 0; c < KCH; c++) {
        mbar_wait(fullb + 8u * s, (uint32_t)ph);

        const uint32_t sa = sbase + (uint32_t)s * STG_BYTES;
        const uint32_t sb = sa + STG_A;

        #pragma unroll
        for (int ks = 0; ks < 4; ks++) {
            uint32_t a[4][4], b[2][4];
            #pragma unroll
            for (int mi = 0; mi < 4; mi++) {
                const int r = wm * 64 + mi * 16 + (lane & 15);
                const int g = 2 * ks + (lane >> 4);
                ldsm_x4(a[mi][0], a[mi][1], a[mi][2], a[mi][3],
                        sa + (uint32_t)r * 128u + (uint32_t)((g ^ (r & 7)) << 4));
            }
            #pragma unroll
            for (int bi = 0; bi < 2; bi++) {
                const int nr = wn * 32 + bi * 16 + (lane & 7) + ((lane >> 4) << 3);
                const int g = 2 * ks + ((lane >> 3) & 1);
                ldsm_x4(b[bi][0], b[bi][1], b[bi][2], b[bi][3],
                        sb + (uint32_t)nr * 128u + (uint32_t)((g ^ (nr & 7)) << 4));
            }
            #pragma unroll
            for (int mi = 0; mi < 4; mi++)
                #pragma unroll
                for (int ni = 0; ni < 4; ni++)
                    mma16816_f16(acc[mi][ni][0], acc[mi][ni][1],
                                 a[mi][0], a[mi][1], a[mi][2], a[mi][3],
                                 b[ni >> 1][(ni & 1) * 2], b[ni >> 1][(ni & 1) * 2 + 1]);
        }

        if (lane == 0) mbar_arrive(emptyb + 8u * s);

        if (tid == 0) {
            const int nx = c + STAGES - 1;
            if (nx < KCH) {
                const int sn = nx % STAGES;
                if (nx >= STAGES)
                    mbar_wait(emptyb + 8u * sn, (uint32_t)(((nx - STAGES) / STAGES) & 1));
                const uint32_t st = sbase + (uint32_t)sn * STG_BYTES;
                mbar_expect_tx(fullb + 8u * sn, STG_BYTES);
                bulk_g2s(st,         baseA + (size_t)nx * CHUNK_STRIDE, STG_A, fullb + 8u * sn);
                bulk_g2s(st + STG_A, baseB + (size_t)nx * CHUNK_STRIDE, STG_B, fullb + 8u * sn);
            }
        }

        if (++s == STAGES) { s = 0; ph ^= 1; }
    }

    // Epilogue: exp(v-1) = ex2(v*log2e - log2e), packed half2; per-row reduce.
    const __half2 l2e  = __float2half2_rn(1.44269504f);
    const __half2 noff = __float2half2_rn(-1.44269504f);
    #pragma unroll
    for (int mi = 0; mi < 4; mi++) {
        __half2 t0 = __float2half2_rn(0.0f);
        __half2 t1 = __float2half2_rn(0.0f);
        #pragma unroll
        for (int ni = 0; ni < 4; ni++) {
            __half2 v0 = *reinterpret_cast<__half2*>(&acc[mi][ni][0]);
            __half2 v1 = *reinterpret_cast<__half2*>(&acc[mi][ni][1]);
            t0 = __hadd2(t0, h2exp2_(__hfma2(v0, l2e, noff)));
            t1 = __hadd2(t1, h2exp2_(__hfma2(v1, l2e, noff)));
        }
        float s0 = __low2float(t0) + __high2float(t0);
        float s1 = __low2float(t1) + __high2float(t1);
        s0 += __shfl_xor_sync(0xffffffffu, s0, 1);
        s0 += __shfl_xor_sync(0xffffffffu, s0, 2);
        s1 += __shfl_xor_sync(0xffffffffu, s1, 1);
        s1 += __shfl_xor_sync(0xffffffffu, s1, 2);
        if ((lane & 3) == 0) {
            const int r = wm * 64 + mi * 16 + (lane >> 2);
            atomicAdd(&rowAcc[r], s0);
            atomicAdd(&rowAcc[r + 8], s1);
        }
    }
    __syncthreads();
    if (tid < TM)
        g_partial[(size_t)ntile * NROW + mtile * TM + tid] = rowAcc[tid];

    if (tid == 0) {
        #pragma unroll
        for (int q = 0; q < STAGES; q++) {
            mbar_inval(fullb + 8u * q);
            mbar_inval(emptyb + 8u * q);
        }
    }
}

// ---------------------------------------------------------------------------
// Kernel 3a: 32 CTAs x 256 threads. Each CTA: 256 rows ->
// sum(log(rowsum) - pos) into g_bsum[block] (fixed-order tree, deterministic).
// ---------------------------------------------------------------------------
__global__ __launch_bounds__(256) void finalize1_kernel() {
    __shared__ float red[256];
    const int row = blockIdx.x * 256 + threadIdx.x;
    float s = 0.0f;
    #pragma unroll
    for (int p = 0; p < NTN; p++) s += g_partial[(size_t)p * NROW + row];
    red[threadIdx.x] = logf(s) - g_pos[row];
    __syncthreads();
    #pragma unroll
    for (int off = 128; off > 0; off >>= 1) {
        if (threadIdx.x < off) red[threadIdx.x] += red[threadIdx.x + off];
        __syncthreads();
    }
    if (threadIdx.x == 0) g_bsum[blockIdx.x] = red[0];
}

// ---------------------------------------------------------------------------
// Kernel 3b: one warp sums the 32 block sums -> mean.
// ---------------------------------------------------------------------------
__global__ void finalize2_kernel(float* __restrict__ out) {
    float s = g_bsum[threadIdx.x];
    #pragma unroll
    for (int o = 16; o; o >>= 1) s += __shfl_xor_sync(0xffffffffu, s, o);
    if (threadIdx.x == 0) out[0] = s / (float)NROW;
}

// ---------------------------------------------------------------------------
extern "C" void kernel_launch(void* const* d_in, const int* in_sizes, int n_in,
                              void* d_out, int out_size) {
    const float* img = (const float*)d_in[0];
    const float* txt = (const float*)d_in[1];
    float* out = (float*)d_out;

    norm_kernel<<<NROW / 8, 256>>>(img, txt);

    cudaFuncSetAttribute(gemm_lse_kernel,
                         cudaFuncAttributeMaxDynamicSharedMemorySize,
                         STAGES * STG_BYTES + 128);
    dim3 grid(NTM, NTN);
    gemm_lse_kernel<<<grid, 256, STAGES * STG_BYTES + 128>>>();

    finalize1_kernel<<<FIN_BLOCKS, 256>>>();
    finalize2_kernel<<<1, 32>>>(out);
}